// round 16
// baseline (speedup 1.0000x reference)
#include <cuda_runtime.h>
#include <math.h>

#define B_   64
#define D_   128
#define N_   500000
#define KP1_ 4096

#define STH        512               // threads per block (both roles)
#define KPT        (KP1_ / STH)      // 8 k's per score thread
#define SCORE_BLKS (2 * B_)          // 128 score blocks
#define COPY_BLKS  1920              // 960 per bank
#define HALF_COPY  (COPY_BLKS / 2)
#define GRID       (SCORE_BLKS + COPY_BLKS)
#define CHUNK4     16667             // ceil(16,000,000 / 960) float4 per copy block
#define CBATCH     8                 // float4 per thread per copy iteration

// ---------------------------------------------------------------------------
// Fused kernel:
//   blocks [0, 128):        score+softmax out[which][b][k]
//   blocks [128, 128+960):  deep-MLP copy of bank A (mem_image)
//   blocks [128+960, 2048): deep-MLP copy of bank B (mem_gene)
// Copy batches 8 independent ld/st pairs per thread (128 B in flight each)
// so the copy saturates DRAM; score gathers hide underneath it.
// ---------------------------------------------------------------------------
__global__ __launch_bounds__(STH, 2)
void fused_kernel(const float* __restrict__ image,
                  const float* __restrict__ gene,
                  const float* __restrict__ mem_image,
                  const float* __restrict__ mem_gene,
                  const int*   __restrict__ idx,
                  float*       __restrict__ out)
{
    const int t = threadIdx.x;

    if (blockIdx.x >= SCORE_BLKS) {
        // ---------------- copy role (per-bank, batched MLP=8) ----------------
        const size_t bank4 = (size_t)N_ * D_ / 4;      // 16,000,000 float4/bank
        const int    cb    = blockIdx.x - SCORE_BLKS;  // 0..1919
        const bool   bankB = (cb >= HALF_COPY);
        const int    lb    = bankB ? cb - HALF_COPY : cb;

        const float4* src = reinterpret_cast<const float4*>(bankB ? mem_gene
                                                                  : mem_image);
        float4* dst = reinterpret_cast<float4*>(out + (size_t)2 * B_ * KP1_)
                      + (bankB ? bank4 : 0);

        size_t i0 = (size_t)lb * CHUNK4;
        size_t i1 = i0 + CHUNK4;
        if (i1 > bank4) i1 = bank4;

        size_t i = i0;
        // full batches: 8 independent loads, then 8 stores
        for (; i + (size_t)CBATCH * STH <= i1; i += (size_t)CBATCH * STH) {
            float4 v[CBATCH];
#pragma unroll
            for (int j = 0; j < CBATCH; ++j)
                v[j] = __ldcs(src + i + t + (size_t)j * STH);
#pragma unroll
            for (int j = 0; j < CBATCH; ++j)
                __stcs(dst + i + t + (size_t)j * STH, v[j]);
        }
        // tail
        for (size_t p = i + t; p < i1; p += STH)
            __stcs(dst + p, __ldcs(src + p));
        return;
    }

    // ---------------- score role ----------------
    const int b     = blockIdx.x & (B_ - 1);
    const int which = blockIdx.x >> 6;

    const float* x   = (which == 0 ? image    : gene)      + b * D_;
    const float* mem = (which == 0 ? mem_gene : mem_image);
    float*       op  = out + (size_t)which * (B_ * KP1_) + (size_t)b * KP1_;

    __shared__ float4 xs[D_ / 4];
    __shared__ float  redm[16];
    __shared__ float  bval;

    const int lane = t & 31;
    const int wid  = t >> 5;

    if (t < D_ / 4) xs[t] = reinterpret_cast<const float4*>(x)[t];
    __syncthreads();

    const int* idxrow = idx + (size_t)b * KP1_;
    const float4* rows[KPT];
#pragma unroll
    for (int j = 0; j < KPT; ++j) {
        int k = t + j * STH;
        rows[j] = reinterpret_cast<const float4*>(mem + (size_t)idxrow[k] * D_);
    }

    float acc[KPT];
#pragma unroll
    for (int j = 0; j < KPT; ++j) acc[j] = 0.0f;

#pragma unroll 4
    for (int d4 = 0; d4 < D_ / 4; ++d4) {
        float4 xv = xs[d4];
#pragma unroll
        for (int j = 0; j < KPT; ++j) {
            float4 r = rows[j][d4];
            acc[j] += r.x * xv.x + r.y * xv.y + r.z * xv.z + r.w * xv.w;
        }
    }

    // ---- block max ----
    float m = acc[0];
#pragma unroll
    for (int j = 1; j < KPT; ++j) m = fmaxf(m, acc[j]);
#pragma unroll
    for (int off = 16; off > 0; off >>= 1)
        m = fmaxf(m, __shfl_xor_sync(0xffffffffu, m, off));
    if (lane == 0) redm[wid] = m;
    __syncthreads();
    if (t < 16) {
        float mm = redm[t];
#pragma unroll
        for (int off = 8; off > 0; off >>= 1)
            mm = fmaxf(mm, __shfl_xor_sync(0x0000ffffu, mm, off));
        if (t == 0) bval = mm;
    }
    __syncthreads();
    const float rowmax = bval;
    __syncthreads();

    // ---- exp + block sum ----
    float e[KPT];
    float s = 0.0f;
#pragma unroll
    for (int j = 0; j < KPT; ++j) {
        e[j] = expf(acc[j] - rowmax);
        s += e[j];
    }
#pragma unroll
    for (int off = 16; off > 0; off >>= 1)
        s += __shfl_xor_sync(0xffffffffu, s, off);
    if (lane == 0) redm[wid] = s;
    __syncthreads();
    if (t < 16) {
        float ss = redm[t];
#pragma unroll
        for (int off = 8; off > 0; off >>= 1)
            ss += __shfl_xor_sync(0x0000ffffu, ss, off);
        if (t == 0) bval = ss;
    }
    __syncthreads();
    const float inv = 1.0f / bval;

#pragma unroll
    for (int j = 0; j < KPT; ++j)
        op[t + j * STH] = e[j] * inv;
}

// ---------------------------------------------------------------------------
// Momentum update of the 64 positive rows into the already-copied banks.
// Duplicate indices: last b wins (matches .at[].set scatter order).
// ---------------------------------------------------------------------------
__global__ void momentum_update_kernel(const float* __restrict__ image,
                                       const float* __restrict__ gene,
                                       const float* __restrict__ mem_image,
                                       const float* __restrict__ mem_gene,
                                       const int*   __restrict__ index,
                                       float*       __restrict__ out)
{
    const int b     = blockIdx.x;
    const int which = blockIdx.y;
    const int myidx = index[b];

    for (int bp = b + 1; bp < B_; ++bp)
        if (index[bp] == myidx) return;   // last-writer-wins

    const float* x   = (which == 0 ? image     : gene)     + b * D_;
    const float* mem = (which == 0 ? mem_image : mem_gene);
    float* dst = out + (size_t)2 * B_ * KP1_
                     + (size_t)which * N_ * D_
                     + (size_t)myidx * D_;

    const int t    = threadIdx.x;   // 128 threads = D_
    const int lane = t & 31;
    const int wid  = t >> 5;

    float v = mem[(size_t)myidx * D_ + t] * 0.5f + x[t] * 0.5f;

    __shared__ float ws[4];
    float s = v * v;
#pragma unroll
    for (int off = 16; off > 0; off >>= 1)
        s += __shfl_xor_sync(0xffffffffu, s, off);
    if (lane == 0) ws[wid] = s;
    __syncthreads();
    float total = ws[0] + ws[1] + ws[2] + ws[3];

    dst[t] = v * rsqrtf(total);
}

// ---------------------------------------------------------------------------
extern "C" void kernel_launch(void* const* d_in, const int* in_sizes, int n_in,
                              void* d_out, int out_size)
{
    const float* image     = (const float*)d_in[0];   // [64,128]
    const float* gene      = (const float*)d_in[1];   // [64,128]
    const float* mem_image = (const float*)d_in[2];   // [500000,128]
    const float* mem_gene  = (const float*)d_in[3];   // [500000,128]
    const int*   index     = (const int*)  d_in[4];   // [64]
    const int*   idx       = (const int*)  d_in[5];   // [64,4096]
    float*       out       = (float*)d_out;

    // 1) Fused copy + score/softmax (copy saturates DRAM; gather hides under it)
    fused_kernel<<<GRID, STH>>>(image, gene, mem_image, mem_gene, idx, out);

    // 2) Momentum scatter-update into the copied banks
    momentum_update_kernel<<<dim3(B_, 2), D_>>>(image, gene, mem_image,
                                                mem_gene, index, out);
}

// round 17
// speedup vs baseline: 1.2352x; 1.2352x over previous
#include <cuda_runtime.h>
#include <math.h>

#define B_   64
#define D_   128
#define N_   500000
#define KP1_ 4096

#define STH   512                 // score kernel threads (16 warps)
#define RPW   (KP1_ / 16)         // 256 rows per warp
#define RU    8                   // rows in flight per warp iteration

// ---------------------------------------------------------------------------
// Score + softmax, warp-per-row gather:
//   out[which][b][k] = softmax_k( dot(mem[idx[b][k]], x[b]) )
// One block per (b, which). Warp w owns rows [w*256, (w+1)*256). Lane l reads
// float4 #l of the row => a warp's LDG touches 4 cache lines (coalesced),
// 8x fewer L1tex wavefronts than lane-per-row. Dot via shfl butterfly.
// ---------------------------------------------------------------------------
__global__ __launch_bounds__(STH, 2)
void score_softmax_v2(const float* __restrict__ image,
                      const float* __restrict__ gene,
                      const float* __restrict__ mem_image,
                      const float* __restrict__ mem_gene,
                      const int*   __restrict__ idx,
                      float*       __restrict__ out)
{
    const int b     = blockIdx.x & (B_ - 1);
    const int which = blockIdx.x >> 6;

    const float* x   = (which == 0 ? image    : gene)      + b * D_;
    const float* mem = (which == 0 ? mem_gene : mem_image);
    float*       op  = out + (size_t)which * (B_ * KP1_) + (size_t)b * KP1_;

    __shared__ float sc[KP1_];     // raw scores, 16 KB
    __shared__ float redm[16];
    __shared__ float bval;

    const int t    = threadIdx.x;
    const int lane = t & 31;
    const int w    = t >> 5;       // warp id, 0..15

    // lane's 16B chunk of the query row (same for every row this warp does)
    const float4 xq = reinterpret_cast<const float4*>(x)[lane];

    const int* idxrow = idx + (size_t)b * KP1_;
    const int  base   = w * RPW;

    for (int r0 = 0; r0 < RPW; r0 += RU) {
        float4 v[RU];
#pragma unroll
        for (int j = 0; j < RU; ++j) {
            const int kk = base + r0 + j;
            const float4* row =
                reinterpret_cast<const float4*>(mem + (size_t)idxrow[kk] * D_);
            v[j] = row[lane];                       // coalesced: 4 lines/warp
        }
#pragma unroll
        for (int j = 0; j < RU; ++j) {
            float d = v[j].x * xq.x + v[j].y * xq.y
                    + v[j].z * xq.z + v[j].w * xq.w;
#pragma unroll
            for (int off = 16; off > 0; off >>= 1)
                d += __shfl_xor_sync(0xffffffffu, d, off);
            if (lane == 0) sc[base + r0 + j] = d;
        }
    }
    __syncthreads();

    // ---- block max over sc[4096] ----
    float sv[8];
    float m = -INFINITY;
#pragma unroll
    for (int j = 0; j < 8; ++j) {
        sv[j] = sc[t + j * STH];
        m = fmaxf(m, sv[j]);
    }
#pragma unroll
    for (int off = 16; off > 0; off >>= 1)
        m = fmaxf(m, __shfl_xor_sync(0xffffffffu, m, off));
    if (lane == 0) redm[w] = m;
    __syncthreads();
    if (t < 16) {
        float mm = redm[t];
#pragma unroll
        for (int off = 8; off > 0; off >>= 1)
            mm = fmaxf(mm, __shfl_xor_sync(0x0000ffffu, mm, off));
        if (t == 0) bval = mm;
    }
    __syncthreads();
    const float rowmax = bval;
    __syncthreads();

    // ---- exp + block sum ----
    float e[8];
    float s = 0.0f;
#pragma unroll
    for (int j = 0; j < 8; ++j) {
        e[j] = expf(sv[j] - rowmax);
        s += e[j];
    }
#pragma unroll
    for (int off = 16; off > 0; off >>= 1)
        s += __shfl_xor_sync(0xffffffffu, s, off);
    if (lane == 0) redm[w] = s;
    __syncthreads();
    if (t < 16) {
        float ss = redm[t];
#pragma unroll
        for (int off = 8; off > 0; off >>= 1)
            ss += __shfl_xor_sync(0x0000ffffu, ss, off);
        if (t == 0) bval = ss;
    }
    __syncthreads();
    const float inv = 1.0f / bval;

#pragma unroll
    for (int j = 0; j < 8; ++j)
        op[t + j * STH] = e[j] * inv;     // coalesced
}

// ---------------------------------------------------------------------------
// Momentum update of the 64 positive rows into the already-copied banks.
// Duplicate indices: last b wins (matches .at[].set scatter order).
// ---------------------------------------------------------------------------
__global__ void momentum_update_kernel(const float* __restrict__ image,
                                       const float* __restrict__ gene,
                                       const float* __restrict__ mem_image,
                                       const float* __restrict__ mem_gene,
                                       const int*   __restrict__ index,
                                       float*       __restrict__ out)
{
    const int b     = blockIdx.x;
    const int which = blockIdx.y;
    const int myidx = index[b];

    for (int bp = b + 1; bp < B_; ++bp)
        if (index[bp] == myidx) return;   // last-writer-wins

    const float* x   = (which == 0 ? image     : gene)     + b * D_;
    const float* mem = (which == 0 ? mem_image : mem_gene);
    float* dst = out + (size_t)2 * B_ * KP1_
                     + (size_t)which * N_ * D_
                     + (size_t)myidx * D_;

    const int t    = threadIdx.x;   // 128 threads = D_
    const int lane = t & 31;
    const int wid  = t >> 5;

    float v = mem[(size_t)myidx * D_ + t] * 0.5f + x[t] * 0.5f;

    __shared__ float ws[4];
    float s = v * v;
#pragma unroll
    for (int off = 16; off > 0; off >>= 1)
        s += __shfl_xor_sync(0xffffffffu, s, off);
    if (lane == 0) ws[wid] = s;
    __syncthreads();
    float total = ws[0] + ws[1] + ws[2] + ws[3];

    dst[t] = v * rsqrtf(total);
}

// ---------------------------------------------------------------------------
extern "C" void kernel_launch(void* const* d_in, const int* in_sizes, int n_in,
                              void* d_out, int out_size)
{
    const float* image     = (const float*)d_in[0];   // [64,128]
    const float* gene      = (const float*)d_in[1];   // [64,128]
    const float* mem_image = (const float*)d_in[2];   // [500000,128]
    const float* mem_gene  = (const float*)d_in[3];   // [500000,128]
    const int*   index     = (const int*)  d_in[4];   // [64]
    const int*   idx       = (const int*)  d_in[5];   // [64,4096]
    float*       out       = (float*)d_out;

    const size_t memElems = (size_t)N_ * D_;
    const size_t memBytes = memElems * sizeof(float);
    float* out_mem_image = out + (size_t)2 * B_ * KP1_;
    float* out_mem_gene  = out_mem_image + memElems;

    // 1) Score + softmax (warp-per-row coalesced gather)
    score_softmax_v2<<<2 * B_, STH>>>(image, gene, mem_image, mem_gene,
                                      idx, out);

    // 2) Bulk bank copies at full memcpy bandwidth (proven 6.7 TB/s)
    cudaMemcpyAsync(out_mem_image, mem_image, memBytes,
                    cudaMemcpyDeviceToDevice, 0);
    cudaMemcpyAsync(out_mem_gene,  mem_gene,  memBytes,
                    cudaMemcpyDeviceToDevice, 0);

    // 3) Momentum scatter-update into the copied banks
    momentum_update_kernel<<<dim3(B_, 2), D_>>>(image, gene, mem_image,
                                                mem_gene, index, out);
}